// round 14
// baseline (speedup 1.0000x reference)
#include <cuda_runtime.h>
#include <cuda_bf16.h>
#include <cuda_fp16.h>
#include <cstdint>

// ---------------- problem constants ----------------
#define BATCH 16
#define DIM   64
#define KNUM  4
#define HW    256
#define KS    5
#define HOUT  127          // (256 + 2 - 5)/2 + 1
#define HWOUT (HOUT*HOUT)  // 16129

// ---------------- device scratch (no allocs allowed) ----------------
__device__ float g_pooled[BATCH * DIM];              // SUMS (divide in att)
__device__ float g_att[BATCH * KNUM];
__device__ float g_aggb[BATCH * DIM];
// transposed fp16 input: [b][row][col][ic]  (134 MB)
__device__ __half g_xt[(size_t)BATCH * HW * HW * DIM];
// conv-friendly weights: [b][tap(25)][oc(64)][ic(64)], single fp16
__device__ __half g_wb[BATCH * 25 * DIM * DIM];
// zero-initialized padding row (device globals are zero-initialized)
__device__ __half g_zero[HW * DIM];

// ---------------- helpers ----------------
__device__ __forceinline__ uint32_t smem_u32(const void* p) {
    uint32_t a;
    asm("{ .reg .u64 t; cvta.to.shared.u64 t, %1; cvt.u32.u64 %0, t; }"
        : "=r"(a) : "l"(p));
    return a;
}

#define LDSM_X4(r0, r1, r2, r3, addr)                                        \
    asm volatile("ldmatrix.sync.aligned.m8n8.x4.shared.b16 {%0,%1,%2,%3}, [%4];" \
                 : "=r"(r0), "=r"(r1), "=r"(r2), "=r"(r3) : "r"(addr))

__device__ __forceinline__ void mma16816(float* c, const uint32_t* a,
                                         const uint32_t* bf) {
    asm volatile(
        "mma.sync.aligned.m16n8k16.row.col.f32.f16.f16.f32 "
        "{%0,%1,%2,%3}, {%4,%5,%6,%7}, {%8,%9}, {%0,%1,%2,%3};"
        : "+f"(c[0]), "+f"(c[1]), "+f"(c[2]), "+f"(c[3])
        : "r"(a[0]), "r"(a[1]), "r"(a[2]), "r"(a[3]), "r"(bf[0]), "r"(bf[1]));
}

__device__ __forceinline__ void cp_async16(uint32_t dst, const void* src) {
    asm volatile("cp.async.ca.shared.global [%0], [%1], 16;"
                 :: "r"(dst), "l"(src));
}
#define CP_COMMIT() asm volatile("cp.async.commit_group;")
#define CP_WAIT0()  asm volatile("cp.async.wait_group 0;")

// ---------------- kernel 0: zero the pooled sums ----------------
__global__ void zero_pool_kernel() {
    g_pooled[threadIdx.x] = 0.f;
}

// ---------------- kernel 1: transpose/convert x + pooled sums ----------------
__global__ __launch_bounds__(256) void transpose_pool_kernel(const float* __restrict__ x) {
    __shared__ uint32_t s[256][33];      // [col][ic_pair] half2
    __shared__ float psum[4][64];
    const int row = blockIdx.x;
    const int b   = blockIdx.y;
    const int t   = threadIdx.x;

    const float* xb = x + (size_t)b * DIM * (HW * HW) + (size_t)row * HW;
    #pragma unroll
    for (int k = 0; k < 8; k++) {
        int idx = t + 256 * k;                 // 0..2047
        int ic0 = idx >> 6;                    // 0..31  (ic pair)
        int c4  = (idx & 63) << 2;             // col base
        const float* p0 = xb + (size_t)(2 * ic0) * (HW * HW) + c4;
        float4 v0 = *(const float4*)p0;
        float4 v1 = *(const float4*)(p0 + (size_t)(HW * HW));
        __half2 h;
        h = __floats2half2_rn(v0.x, v1.x); s[c4 + 0][ic0] = *(uint32_t*)&h;
        h = __floats2half2_rn(v0.y, v1.y); s[c4 + 1][ic0] = *(uint32_t*)&h;
        h = __floats2half2_rn(v0.z, v1.z); s[c4 + 2][ic0] = *(uint32_t*)&h;
        h = __floats2half2_rn(v0.w, v1.w); s[c4 + 3][ic0] = *(uint32_t*)&h;
    }
    __syncthreads();

    {
        int ic = t & 63, part = t >> 6;
        float sum = 0.f;
        for (int c = part * 64; c < part * 64 + 64; c++) {
            uint32_t u = s[c][ic >> 1];
            __half2 h = *(__half2*)&u;
            sum += (ic & 1) ? __high2float(h) : __low2float(h);
        }
        psum[part][ic] = sum;
    }
    __syncthreads();
    if (t < 64)
        atomicAdd(&g_pooled[b * DIM + t],
                  psum[0][t] + psum[1][t] + psum[2][t] + psum[3][t]);

    __half* dst = g_xt + (((size_t)b * HW + row) * HW) * DIM;
    #pragma unroll
    for (int o = 0; o < 8; o++) {
        int oi = t + 256 * o;                  // 0..2047
        int col = oi >> 3, q = oi & 7;
        uint2 w0, w1;
        w0.x = s[col][q * 4 + 0]; w0.y = s[col][q * 4 + 1];
        w1.x = s[col][q * 4 + 2]; w1.y = s[col][q * 4 + 3];
        *(uint2*)(dst + col * DIM + q * 8)     = w0;
        *(uint2*)(dst + col * DIM + q * 8 + 4) = w1;
    }
}

// ---------------- kernel 2: attention + agg_b ----------------
__global__ void att_kernel(const float* __restrict__ fc1_w, const float* __restrict__ fc1_b,
                           const float* __restrict__ fc2_w, const float* __restrict__ fc2_b,
                           const float* __restrict__ bias) {
    __shared__ float att_s[BATCH][KNUM];
    int t = threadIdx.x;
    if (t < BATCH) {
        const float inv_hw = 1.0f / (float)(HW * HW);
        float a[KNUM];
        #pragma unroll
        for (int k = 0; k < KNUM; k++) {
            float s = fc1_b[k];
            for (int c = 0; c < DIM; c++)
                s += (g_pooled[t * DIM + c] * inv_hw) * fc1_w[k * DIM + c];
            a[k] = s > 0.f ? s : 0.f;
        }
        float l[KNUM], mx = -1e30f;
        #pragma unroll
        for (int k = 0; k < KNUM; k++) {
            float s = fc2_b[k];
            #pragma unroll
            for (int j = 0; j < KNUM; j++) s += a[j] * fc2_w[k * KNUM + j];
            l[k] = s;
            mx = fmaxf(mx, s);
        }
        float den = 0.f;
        #pragma unroll
        for (int k = 0; k < KNUM; k++) { l[k] = __expf(l[k] - mx); den += l[k]; }
        float inv = 1.0f / den;
        #pragma unroll
        for (int k = 0; k < KNUM; k++) {
            float v = l[k] * inv;
            att_s[t][k] = v;
            g_att[t * KNUM + k] = v;
        }
    }
    __syncthreads();
    for (int idx = t; idx < BATCH * DIM; idx += blockDim.x) {
        int b = idx / DIM, o = idx % DIM;
        float s = 0.f;
        #pragma unroll
        for (int k = 0; k < KNUM; k++) s += att_s[b][k] * bias[k * DIM + o];
        g_aggb[idx] = s;
    }
}

// ---------------- kernel 3: agg_w mix + w_ret + fp16 weights (coalesced) ----------------
__global__ __launch_bounds__(256) void aggw_kernel(const float* __restrict__ weight,
                                                   float* __restrict__ wret) {
    __shared__ float v[DIM * KS * KS];       // 1600 floats, [i*25+p]
    const int PER_B = DIM * DIM * KS * KS;   // 102400
    const int o = blockIdx.x;
    const int b = blockIdx.y;
    const float a0 = g_att[b * 4 + 0], a1 = g_att[b * 4 + 1];
    const float a2 = g_att[b * 4 + 2], a3 = g_att[b * 4 + 3];

    const float* w0 = weight + (size_t)o * (DIM * KS * KS);
    for (int j = threadIdx.x; j < DIM * KS * KS; j += 256) {
        v[j] = a0 * w0[j]
             + a1 * w0[PER_B + j]
             + a2 * w0[2 * PER_B + j]
             + a3 * w0[3 * PER_B + j];
    }
    __syncthreads();

    float* wr = wret + ((size_t)(b * DIM + o)) * (KS * KS * DIM);
    for (int j = threadIdx.x; j < DIM * KS * KS; j += 256) {
        int p = j >> 6, i = j & 63;          // j = p*64 + i
        float val = v[i * (KS * KS) + p];
        wr[j] = val;                          // [p][i] contiguous
        g_wb[((size_t)(b * 25 + p) * DIM + o) * DIM + i] = __float2half(val);
    }
}

// ---------------- kernel 4: mma.sync implicit-GEMM conv (v7: 2-row CTA) ----------------
// CTA = (ho pair, b), 256 threads = 8 warps. Warps 0-3 -> row 2bx (A set0),
// warps 4-7 -> row 2bx+1 (A set1). B staged once, shared by both groups.
#define APITCH 144
#define PLANE  (130 * APITCH)       // 18720 B, rows 0 and 129 = zero guards
// A set g at  g*2*PLANE :  even plane +0, odd plane +PLANE
#define B_OFF   (4 * PLANE)         // 74880; 2 bufs x 9216 = 18432
#define BIAS_OFF (B_OFF + 18432)    // 93312
#define CONV_SMEM 93568

__global__ __launch_bounds__(256, 2) void conv_mma_kernel(float* __restrict__ out) {
    extern __shared__ char smem[];
    const uint32_t sbase = smem_u32(smem);
    const int b   = blockIdx.y;
    const int hoA = blockIdx.x * 2;
    const int t   = threadIdx.x;
    const int wid = t >> 5;
    const int l   = t & 31;
    const int g   = wid >> 2;              // row group 0/1
    const int mbase = (wid & 3) * 32;
    const int ho  = hoA + g;               // may be 127 (stores guarded)

    float acc[2][8][4];
    #pragma unroll
    for (int f = 0; f < 2; f++)
        #pragma unroll
        for (int nf = 0; nf < 8; nf++)
            #pragma unroll
            for (int q = 0; q < 4; q++) acc[f][nf][q] = 0.f;

    // zero guard rows (rows 0 and 129 of all 4 planes) + stage bias
    for (int i = t; i < 288; i += 256) {           // 4 planes * 2 rows * 36 words
        int pl = i / 72;
        int r  = (i % 72) / 36;
        int w  = i % 36;
        *(uint32_t*)(smem + pl * PLANE + (r ? 129 : 0) * APITCH + w * 4) = 0;
    }
    if (t < DIM) ((float*)(smem + BIAS_OFF))[t] = g_aggb[b * DIM + t];

    const __half* wbb = g_wb + (size_t)(b * 25) * (DIM * DIM);

    // per-lane ldmatrix bases
    const uint32_t lrow = (uint32_t)(l & 15);
    const uint32_t lk16 = (uint32_t)(l >> 4) * 16;
    const uint32_t aRowOff = (uint32_t)g * (2 * PLANE)
                           + (uint32_t)(mbase + (int)lrow) * APITCH + lk16;
    const uint32_t bRowOff = lrow * APITCH + lk16;

    // B cp.async mapping: 512 chunks / 256 threads = 2 per thread
    const int oc0 = t >> 3;                 // 0..31
    const int q0  = t & 7;

    for (int kh = 0; kh < KS; kh++) {
        const int rA = 2 * hoA - 1 + kh;    // row for group 0
        __syncthreads();                    // prior readers of A planes + B buf0 done

        // ---- A staging: 4096 x 16B cp.async (2 rows) ----
        {
            #pragma unroll
            for (int k = 0; k < 16; k++) {
                int c = t + 256 * k;               // 0..4095
                int si  = c >> 11;                 // set 0/1
                int cc  = c & 2047;
                int col = cc >> 3, q = cc & 7;
                int row = rA + 2 * si;
                const __half* src = (row >= 0 && row < HW)
                    ? g_xt + (((size_t)b * HW + row) * HW) * DIM + col * DIM + q * 8
                    : g_zero + col * DIM + q * 8;
                uint32_t dst = sbase + (uint32_t)si * (2 * PLANE)
                             + ((col & 1) ? PLANE : 0)
                             + (uint32_t)((col >> 1) + 1) * APITCH + q * 16;
                cp_async16(dst, src);
            }
        }
        // ---- B first tap of this kh into buf0 (same group) ----
        {
            const __half* src = wbb + (size_t)(kh * KS) * (DIM * DIM);
            uint32_t dbase = sbase + B_OFF;
            #pragma unroll
            for (int it = 0; it < 2; it++) {
                int oc = oc0 + it * 32;
                cp_async16(dbase + oc * APITCH + q0 * 16, src + oc * DIM + q0 * 8);
            }
        }
        CP_COMMIT();

        for (int kw = 0; kw < KS; kw++) {
            CP_WAIT0();
            __syncthreads();                   // staged data visible to all warps

            if (kw < KS - 1) {
                const __half* src = wbb + (size_t)(kh * KS + kw + 1) * (DIM * DIM);
                uint32_t dbase = sbase + B_OFF + ((kw + 1) & 1) * 9216;
                #pragma unroll
                for (int it = 0; it < 2; it++) {
                    int oc = oc0 + it * 32;
                    cp_async16(dbase + oc * APITCH + q0 * 16, src + oc * DIM + q0 * 8);
                }
                CP_COMMIT();
            }

            const int roff = (kw + 1) >> 1;                 // {0,1,1,2,2}
            const uint32_t aBase = sbase + ((kw & 1) ? 0 : PLANE)   // even/odd plane
                                 + (uint32_t)roff * APITCH + aRowOff;
            const uint32_t bBase = sbase + B_OFF + (kw & 1) * 9216 + bRowOff;

            // ---- paired s-steps: batch 12 LDSM, then 32 MMAs ----
            #pragma unroll
            for (int sp = 0; sp < 2; sp++) {
                uint32_t ah[2][2][4];          // [s-in-pair][f]
                uint32_t bbf[2][4][4];         // [s-in-pair][nb]
                #pragma unroll
                for (int sh = 0; sh < 2; sh++) {
                    const int s = sp * 2 + sh;
                    #pragma unroll
                    for (int f = 0; f < 2; f++) {
                        uint32_t ra = aBase + (uint32_t)f * (16 * APITCH) + s * 32;
                        LDSM_X4(ah[sh][f][0], ah[sh][f][1], ah[sh][f][2], ah[sh][f][3], ra);
                    }
                    #pragma unroll
                    for (int nb = 0; nb < 4; nb++) {
                        uint32_t rb = bBase + (uint32_t)nb * (16 * APITCH) + s * 32;
                        LDSM_X4(bbf[sh][nb][0], bbf[sh][nb][1], bbf[sh][nb][2], bbf[sh][nb][3], rb);
                    }
                }
                #pragma unroll
                for (int sh = 0; sh < 2; sh++)
                    #pragma unroll
                    for (int nb = 0; nb < 4; nb++) {
                        uint32_t bf0[2] = {bbf[sh][nb][0], bbf[sh][nb][2]};
                        uint32_t bf1[2] = {bbf[sh][nb][1], bbf[sh][nb][3]};
                        #pragma unroll
                        for (int f = 0; f < 2; f++) {
                            mma16816(acc[f][nb * 2],     ah[sh][f], bf0);
                            mma16816(acc[f][nb * 2 + 1], ah[sh][f], bf1);
                        }
                    }
            }
        }
    }

    // ---- epilogue: +bias, store ----
    __syncthreads();
    const float* bias_s = (const float*)(smem + BIAS_OFF);
    const size_t obase = (size_t)b * DIM * HWOUT + (size_t)ho * HOUT;
    const int wo_l = l >> 2;
    const int oc_l = 2 * (l & 3);
    if (ho < HOUT) {
        #pragma unroll
        for (int f = 0; f < 2; f++) {
            int w1 = mbase + f * 16 + wo_l;
            int w2 = w1 + 8;
            #pragma unroll
            for (int nf = 0; nf < 8; nf++) {
                int oc = nf * 8 + oc_l;
                float b0 = bias_s[oc], b1 = bias_s[oc + 1];
                const float* c = acc[f][nf];
                if (w1 < HOUT) {
                    out[obase + (size_t)oc * HWOUT + w1]       = c[0] + b0;
                    out[obase + (size_t)(oc + 1) * HWOUT + w1] = c[1] + b1;
                }
                if (w2 < HOUT) {
                    out[obase + (size_t)oc * HWOUT + w2]       = c[2] + b0;
                    out[obase + (size_t)(oc + 1) * HWOUT + w2] = c[3] + b1;
                }
            }
        }
    }
}

// ---------------- launch ----------------
extern "C" void kernel_launch(void* const* d_in, const int* in_sizes, int n_in,
                              void* d_out, int out_size) {
    const float* x      = (const float*)d_in[0];
    const float* fc1_w  = (const float*)d_in[1];
    const float* fc1_b  = (const float*)d_in[2];
    const float* fc2_w  = (const float*)d_in[3];
    const float* fc2_b  = (const float*)d_in[4];
    const float* weight = (const float*)d_in[5];
    const float* bias   = (const float*)d_in[6];
    float* out = (float*)d_out;

    const size_t WRET_ELEMS = (size_t)BATCH * DIM * KS * KS * DIM;  // 1,638,400
    float* wret = out + ((size_t)out_size - WRET_ELEMS);

    cudaFuncSetAttribute(conv_mma_kernel,
                         cudaFuncAttributeMaxDynamicSharedMemorySize, CONV_SMEM);

    zero_pool_kernel<<<1, BATCH * DIM>>>();
    transpose_pool_kernel<<<dim3(HW, BATCH), 256>>>(x);
    att_kernel<<<1, 256>>>(fc1_w, fc1_b, fc2_w, fc2_b, bias);
    aggw_kernel<<<dim3(DIM, BATCH), 256>>>(weight, wret);
    conv_mma_kernel<<<dim3(64, BATCH), 256, CONV_SMEM>>>(out);
}

// round 15
// speedup vs baseline: 1.0060x; 1.0060x over previous
#include <cuda_runtime.h>
#include <cuda_bf16.h>
#include <cuda_fp16.h>
#include <cstdint>

// ---------------- problem constants ----------------
#define BATCH 16
#define DIM   64
#define KNUM  4
#define HW    256
#define KS    5
#define HOUT  127          // (256 + 2 - 5)/2 + 1
#define HWOUT (HOUT*HOUT)  // 16129

// ---------------- device scratch (no allocs allowed) ----------------
__device__ float g_pooled[BATCH * DIM];              // SUMS (divide in att)
__device__ float g_att[BATCH * KNUM];
__device__ float g_aggb[BATCH * DIM];
// transposed fp16 input: [b][row][col][ic]  (134 MB)
__device__ __half g_xt[(size_t)BATCH * HW * HW * DIM];
// conv-friendly weights: [b][tap(25)][oc(64)][ic(64)], single fp16
__device__ __half g_wb[BATCH * 25 * DIM * DIM];
// zero-initialized padding row (device globals are zero-initialized)
__device__ __half g_zero[HW * DIM];

// ---------------- helpers ----------------
__device__ __forceinline__ uint32_t smem_u32(const void* p) {
    uint32_t a;
    asm("{ .reg .u64 t; cvta.to.shared.u64 t, %1; cvt.u32.u64 %0, t; }"
        : "=r"(a) : "l"(p));
    return a;
}

#define LDSM_X4(r0, r1, r2, r3, addr)                                        \
    asm volatile("ldmatrix.sync.aligned.m8n8.x4.shared.b16 {%0,%1,%2,%3}, [%4];" \
                 : "=r"(r0), "=r"(r1), "=r"(r2), "=r"(r3) : "r"(addr))

__device__ __forceinline__ void mma16816(float* c, const uint32_t* a,
                                         const uint32_t* bf) {
    asm volatile(
        "mma.sync.aligned.m16n8k16.row.col.f32.f16.f16.f32 "
        "{%0,%1,%2,%3}, {%4,%5,%6,%7}, {%8,%9}, {%0,%1,%2,%3};"
        : "+f"(c[0]), "+f"(c[1]), "+f"(c[2]), "+f"(c[3])
        : "r"(a[0]), "r"(a[1]), "r"(a[2]), "r"(a[3]), "r"(bf[0]), "r"(bf[1]));
}

// .cg: 16B-only, bypasses L1 allocation (we never re-read staged data via L1)
__device__ __forceinline__ void cp_async16(uint32_t dst, const void* src) {
    asm volatile("cp.async.cg.shared.global [%0], [%1], 16;"
                 :: "r"(dst), "l"(src));
}
#define CP_COMMIT() asm volatile("cp.async.commit_group;")
#define CP_WAIT0()  asm volatile("cp.async.wait_group 0;")

// ---------------- kernel 0: zero the pooled sums ----------------
__global__ void zero_pool_kernel() {
    g_pooled[threadIdx.x] = 0.f;
}

// ---------------- kernel 1: transpose/convert x + pooled sums ----------------
__global__ __launch_bounds__(256) void transpose_pool_kernel(const float* __restrict__ x) {
    __shared__ uint32_t s[256][33];      // [col][ic_pair] half2
    __shared__ float psum[4][64];
    const int row = blockIdx.x;
    const int b   = blockIdx.y;
    const int t   = threadIdx.x;

    const float* xb = x + (size_t)b * DIM * (HW * HW) + (size_t)row * HW;
    #pragma unroll
    for (int k = 0; k < 8; k++) {
        int idx = t + 256 * k;                 // 0..2047
        int ic0 = idx >> 6;                    // 0..31  (ic pair)
        int c4  = (idx & 63) << 2;             // col base
        const float* p0 = xb + (size_t)(2 * ic0) * (HW * HW) + c4;
        float4 v0 = *(const float4*)p0;
        float4 v1 = *(const float4*)(p0 + (size_t)(HW * HW));
        __half2 h;
        h = __floats2half2_rn(v0.x, v1.x); s[c4 + 0][ic0] = *(uint32_t*)&h;
        h = __floats2half2_rn(v0.y, v1.y); s[c4 + 1][ic0] = *(uint32_t*)&h;
        h = __floats2half2_rn(v0.z, v1.z); s[c4 + 2][ic0] = *(uint32_t*)&h;
        h = __floats2half2_rn(v0.w, v1.w); s[c4 + 3][ic0] = *(uint32_t*)&h;
    }
    __syncthreads();

    {
        int ic = t & 63, part = t >> 6;
        float sum = 0.f;
        for (int c = part * 64; c < part * 64 + 64; c++) {
            uint32_t u = s[c][ic >> 1];
            __half2 h = *(__half2*)&u;
            sum += (ic & 1) ? __high2float(h) : __low2float(h);
        }
        psum[part][ic] = sum;
    }
    __syncthreads();
    if (t < 64)
        atomicAdd(&g_pooled[b * DIM + t],
                  psum[0][t] + psum[1][t] + psum[2][t] + psum[3][t]);

    __half* dst = g_xt + (((size_t)b * HW + row) * HW) * DIM;
    #pragma unroll
    for (int o = 0; o < 8; o++) {
        int oi = t + 256 * o;                  // 0..2047
        int col = oi >> 3, q = oi & 7;
        uint2 w0, w1;
        w0.x = s[col][q * 4 + 0]; w0.y = s[col][q * 4 + 1];
        w1.x = s[col][q * 4 + 2]; w1.y = s[col][q * 4 + 3];
        *(uint2*)(dst + col * DIM + q * 8)     = w0;
        *(uint2*)(dst + col * DIM + q * 8 + 4) = w1;
    }
}

// ---------------- kernel 2: attention + agg_b ----------------
__global__ void att_kernel(const float* __restrict__ fc1_w, const float* __restrict__ fc1_b,
                           const float* __restrict__ fc2_w, const float* __restrict__ fc2_b,
                           const float* __restrict__ bias) {
    __shared__ float att_s[BATCH][KNUM];
    int t = threadIdx.x;
    if (t < BATCH) {
        const float inv_hw = 1.0f / (float)(HW * HW);
        float a[KNUM];
        #pragma unroll
        for (int k = 0; k < KNUM; k++) {
            float s = fc1_b[k];
            for (int c = 0; c < DIM; c++)
                s += (g_pooled[t * DIM + c] * inv_hw) * fc1_w[k * DIM + c];
            a[k] = s > 0.f ? s : 0.f;
        }
        float l[KNUM], mx = -1e30f;
        #pragma unroll
        for (int k = 0; k < KNUM; k++) {
            float s = fc2_b[k];
            #pragma unroll
            for (int j = 0; j < KNUM; j++) s += a[j] * fc2_w[k * KNUM + j];
            l[k] = s;
            mx = fmaxf(mx, s);
        }
        float den = 0.f;
        #pragma unroll
        for (int k = 0; k < KNUM; k++) { l[k] = __expf(l[k] - mx); den += l[k]; }
        float inv = 1.0f / den;
        #pragma unroll
        for (int k = 0; k < KNUM; k++) {
            float v = l[k] * inv;
            att_s[t][k] = v;
            g_att[t * KNUM + k] = v;
        }
    }
    __syncthreads();
    for (int idx = t; idx < BATCH * DIM; idx += blockDim.x) {
        int b = idx / DIM, o = idx % DIM;
        float s = 0.f;
        #pragma unroll
        for (int k = 0; k < KNUM; k++) s += att_s[b][k] * bias[k * DIM + o];
        g_aggb[idx] = s;
    }
}

// ---------------- kernel 3: agg_w mix + w_ret + fp16 weights (coalesced) ----------------
__global__ __launch_bounds__(256) void aggw_kernel(const float* __restrict__ weight,
                                                   float* __restrict__ wret) {
    __shared__ float v[DIM * KS * KS];       // 1600 floats, [i*25+p]
    const int PER_B = DIM * DIM * KS * KS;   // 102400
    const int o = blockIdx.x;
    const int b = blockIdx.y;
    const float a0 = g_att[b * 4 + 0], a1 = g_att[b * 4 + 1];
    const float a2 = g_att[b * 4 + 2], a3 = g_att[b * 4 + 3];

    const float* w0 = weight + (size_t)o * (DIM * KS * KS);
    for (int j = threadIdx.x; j < DIM * KS * KS; j += 256) {
        v[j] = a0 * w0[j]
             + a1 * w0[PER_B + j]
             + a2 * w0[2 * PER_B + j]
             + a3 * w0[3 * PER_B + j];
    }
    __syncthreads();

    float* wr = wret + ((size_t)(b * DIM + o)) * (KS * KS * DIM);
    for (int j = threadIdx.x; j < DIM * KS * KS; j += 256) {
        int p = j >> 6, i = j & 63;          // j = p*64 + i
        float val = v[i * (KS * KS) + p];
        wr[j] = val;                          // [p][i] contiguous
        g_wb[((size_t)(b * 25 + p) * DIM + o) * DIM + i] = __float2half(val);
    }
}

// ---------------- kernel 4: mma.sync implicit-GEMM conv (v8: s-pipelined) ----------------
// CTA = (ho pair, b), 256 threads = 8 warps. Warps 0-3 -> row 2bx (A set0),
// warps 4-7 -> row 2bx+1 (A set1). B staged once, shared by both groups.
// Inner loop: single-s software pipeline (double-buffered fragment registers).
#define APITCH 144
#define PLANE  (130 * APITCH)       // 18720 B, rows 0 and 129 = zero guards
#define B_OFF   (4 * PLANE)         // 74880; 2 bufs x 9216 = 18432
#define BIAS_OFF (B_OFF + 18432)    // 93312
#define CONV_SMEM 93568

__global__ __launch_bounds__(256, 2) void conv_mma_kernel(float* __restrict__ out) {
    extern __shared__ char smem[];
    const uint32_t sbase = smem_u32(smem);
    const int b   = blockIdx.y;
    const int hoA = blockIdx.x * 2;
    const int t   = threadIdx.x;
    const int wid = t >> 5;
    const int l   = t & 31;
    const int g   = wid >> 2;              // row group 0/1
    const int mbase = (wid & 3) * 32;
    const int ho  = hoA + g;               // may be 127 (stores guarded)

    float acc[2][8][4];
    #pragma unroll
    for (int f = 0; f < 2; f++)
        #pragma unroll
        for (int nf = 0; nf < 8; nf++)
            #pragma unroll
            for (int q = 0; q < 4; q++) acc[f][nf][q] = 0.f;

    // zero guard rows (rows 0 and 129 of all 4 planes) + stage bias
    for (int i = t; i < 288; i += 256) {           // 4 planes * 2 rows * 36 words
        int pl = i / 72;
        int r  = (i % 72) / 36;
        int w  = i % 36;
        *(uint32_t*)(smem + pl * PLANE + (r ? 129 : 0) * APITCH + w * 4) = 0;
    }
    if (t < DIM) ((float*)(smem + BIAS_OFF))[t] = g_aggb[b * DIM + t];

    const __half* wbb = g_wb + (size_t)(b * 25) * (DIM * DIM);

    // per-lane ldmatrix bases
    const uint32_t lrow = (uint32_t)(l & 15);
    const uint32_t lk16 = (uint32_t)(l >> 4) * 16;
    const uint32_t aRowOff = (uint32_t)g * (2 * PLANE)
                           + (uint32_t)(mbase + (int)lrow) * APITCH + lk16;
    const uint32_t bRowOff = lrow * APITCH + lk16;

    // B cp.async mapping: 512 chunks / 256 threads = 2 per thread
    const int oc0 = t >> 3;                 // 0..31
    const int q0  = t & 7;

    for (int kh = 0; kh < KS; kh++) {
        const int rA = 2 * hoA - 1 + kh;    // row for group 0
        __syncthreads();                    // prior readers of A planes + B buf0 done

        // ---- A staging: 4096 x 16B cp.async (2 rows) ----
        {
            #pragma unroll
            for (int k = 0; k < 16; k++) {
                int c = t + 256 * k;               // 0..4095
                int si  = c >> 11;                 // set 0/1
                int cc  = c & 2047;
                int col = cc >> 3, q = cc & 7;
                int row = rA + 2 * si;
                const __half* src = (row >= 0 && row < HW)
                    ? g_xt + (((size_t)b * HW + row) * HW) * DIM + col * DIM + q * 8
                    : g_zero + col * DIM + q * 8;
                uint32_t dst = sbase + (uint32_t)si * (2 * PLANE)
                             + ((col & 1) ? PLANE : 0)
                             + (uint32_t)((col >> 1) + 1) * APITCH + q * 16;
                cp_async16(dst, src);
            }
        }
        // ---- B first tap of this kh into buf0 (same group) ----
        {
            const __half* src = wbb + (size_t)(kh * KS) * (DIM * DIM);
            uint32_t dbase = sbase + B_OFF;
            #pragma unroll
            for (int it = 0; it < 2; it++) {
                int oc = oc0 + it * 32;
                cp_async16(dbase + oc * APITCH + q0 * 16, src + oc * DIM + q0 * 8);
            }
        }
        CP_COMMIT();

        for (int kw = 0; kw < KS; kw++) {
            CP_WAIT0();
            __syncthreads();                   // staged data visible to all warps

            if (kw < KS - 1) {
                const __half* src = wbb + (size_t)(kh * KS + kw + 1) * (DIM * DIM);
                uint32_t dbase = sbase + B_OFF + ((kw + 1) & 1) * 9216;
                #pragma unroll
                for (int it = 0; it < 2; it++) {
                    int oc = oc0 + it * 32;
                    cp_async16(dbase + oc * APITCH + q0 * 16, src + oc * DIM + q0 * 8);
                }
                CP_COMMIT();
            }

            const int roff = (kw + 1) >> 1;                 // {0,1,1,2,2}
            const uint32_t aBase = sbase + ((kw & 1) ? 0 : PLANE)   // even/odd plane
                                 + (uint32_t)roff * APITCH + aRowOff;
            const uint32_t bBase = sbase + B_OFF + (kw & 1) * 9216 + bRowOff;

            // ---- single-s software pipeline: LDSM(s+1) issued before MMA(s) ----
            uint32_t ah[2][2][4];             // [buf][f]
            uint32_t bbf[2][4][4];            // [buf][nb]
            // prologue: load s=0 into buf 0
            #pragma unroll
            for (int f = 0; f < 2; f++) {
                uint32_t ra = aBase + (uint32_t)f * (16 * APITCH);
                LDSM_X4(ah[0][f][0], ah[0][f][1], ah[0][f][2], ah[0][f][3], ra);
            }
            #pragma unroll
            for (int nb = 0; nb < 4; nb++) {
                uint32_t rb = bBase + (uint32_t)nb * (16 * APITCH);
                LDSM_X4(bbf[0][nb][0], bbf[0][nb][1], bbf[0][nb][2], bbf[0][nb][3], rb);
            }
            #pragma unroll
            for (int s = 0; s < 4; s++) {
                const int cur = s & 1, nxt = cur ^ 1;
                if (s < 3) {                  // prefetch s+1 before MMAs of s
                    #pragma unroll
                    for (int f = 0; f < 2; f++) {
                        uint32_t ra = aBase + (uint32_t)f * (16 * APITCH) + (s + 1) * 32;
                        LDSM_X4(ah[nxt][f][0], ah[nxt][f][1], ah[nxt][f][2], ah[nxt][f][3], ra);
                    }
                    #pragma unroll
                    for (int nb = 0; nb < 4; nb++) {
                        uint32_t rb = bBase + (uint32_t)nb * (16 * APITCH) + (s + 1) * 32;
                        LDSM_X4(bbf[nxt][nb][0], bbf[nxt][nb][1], bbf[nxt][nb][2], bbf[nxt][nb][3], rb);
                    }
                }
                #pragma unroll
                for (int nb = 0; nb < 4; nb++) {
                    uint32_t bf0[2] = {bbf[cur][nb][0], bbf[cur][nb][2]};
                    uint32_t bf1[2] = {bbf[cur][nb][1], bbf[cur][nb][3]};
                    #pragma unroll
                    for (int f = 0; f < 2; f++) {
                        mma16816(acc[f][nb * 2],     ah[cur][f], bf0);
                        mma16816(acc[f][nb * 2 + 1], ah[cur][f], bf1);
                    }
                }
            }
        }
    }

    // ---- epilogue: +bias, store ----
    __syncthreads();
    const float* bias_s = (const float*)(smem + BIAS_OFF);
    const size_t obase = (size_t)b * DIM * HWOUT + (size_t)ho * HOUT;
    const int wo_l = l >> 2;
    const int oc_l = 2 * (l & 3);
    if (ho < HOUT) {
        #pragma unroll
        for (int f = 0; f < 2; f++) {
            int w1 = mbase + f * 16 + wo_l;
            int w2 = w1 + 8;
            #pragma unroll
            for (int nf = 0; nf < 8; nf++) {
                int oc = nf * 8 + oc_l;
                float b0 = bias_s[oc], b1 = bias_s[oc + 1];
                const float* c = acc[f][nf];
                if (w1 < HOUT) {
                    out[obase + (size_t)oc * HWOUT + w1]       = c[0] + b0;
                    out[obase + (size_t)(oc + 1) * HWOUT + w1] = c[1] + b1;
                }
                if (w2 < HOUT) {
                    out[obase + (size_t)oc * HWOUT + w2]       = c[2] + b0;
                    out[obase + (size_t)(oc + 1) * HWOUT + w2] = c[3] + b1;
                }
            }
        }
    }
}

// ---------------- launch ----------------
extern "C" void kernel_launch(void* const* d_in, const int* in_sizes, int n_in,
                              void* d_out, int out_size) {
    const float* x      = (const float*)d_in[0];
    const float* fc1_w  = (const float*)d_in[1];
    const float* fc1_b  = (const float*)d_in[2];
    const float* fc2_w  = (const float*)d_in[3];
    const float* fc2_b  = (const float*)d_in[4];
    const float* weight = (const float*)d_in[5];
    const float* bias   = (const float*)d_in[6];
    float* out = (float*)d_out;

    const size_t WRET_ELEMS = (size_t)BATCH * DIM * KS * KS * DIM;  // 1,638,400
    float* wret = out + ((size_t)out_size - WRET_ELEMS);

    cudaFuncSetAttribute(conv_mma_kernel,
                         cudaFuncAttributeMaxDynamicSharedMemorySize, CONV_SMEM);

    zero_pool_kernel<<<1, BATCH * DIM>>>();
    transpose_pool_kernel<<<dim3(HW, BATCH), 256>>>(x);
    att_kernel<<<1, 256>>>(fc1_w, fc1_b, fc2_w, fc2_b, bias);
    aggw_kernel<<<dim3(DIM, BATCH), 256>>>(weight, wret);
    conv_mma_kernel<<<dim3(64, BATCH), 256, CONV_SMEM>>>(out);
}